// round 17
// baseline (speedup 1.0000x reference)
#include <cuda_runtime.h>

#define N_VOX        1024
#define NUM_RAYS     2048
#define N_SH         9
#define NS           8
#define RAYS_PER_CTA 4
#define THREADS      256
#define VPT          (N_VOX / THREADS)     // 4 voxels resident per thread
#define CAP          128
#define EARLY_STOP_T 0.01f
#define FAR_PLANE    100.0f
#define FULL         0xffffffffu

// float -> order-preserving uint32 (ascending float == ascending uint)
__device__ __forceinline__ unsigned f2u(float f) {
    unsigned u = __float_as_uint(f);
    return (u & 0x80000000u) ? ~u : (u | 0x80000000u);
}

__device__ __forceinline__ float fast_sigmoid(float a) {
    return __fdividef(1.0f, 1.0f + __expf(-a));
}

__global__ void __launch_bounds__(THREADS)
voxel_raster_kernel(const float* __restrict__ positions,   // [N,3]
                    const float* __restrict__ sizes,       // [N]
                    const float* __restrict__ densities,   // [N]
                    const float* __restrict__ colors,      // [N, 27]
                    const float* __restrict__ ray_o,       // [B,3]
                    const float* __restrict__ ray_d,       // [B,3]
                    float* __restrict__ out)               // rgb[3B] | depth[B] | weight[B]
{
    __shared__ float s_ray[RAYS_PER_CTA][6];               // ix,iy,iz,nx,ny,nz
    __shared__ int   s_cnt[RAYS_PER_CTA];
    __shared__ unsigned long long s_keys[RAYS_PER_CTA][CAP];
    __shared__ float s_tw[RAYS_PER_CTA][CAP];              // tf (phase1) -> ws (tail)
    __shared__ float s_dp[RAYS_PER_CTA][CAP];
    __shared__ float s_cr[RAYS_PER_CTA][CAP];
    __shared__ float s_cg[RAYS_PER_CTA][CAP];
    __shared__ float s_cb[RAYS_PER_CTA][CAP];

    const int tid  = threadIdx.x;
    const int warp = tid >> 5;
    const int lane = tid & 31;

    // ---- ray setup: thread r computes ray r's params (exact IEEE divides) ----
    if (tid < RAYS_PER_CTA) {
        const int rb = blockIdx.x * RAYS_PER_CTA + tid;
        const float ox = ray_o[rb * 3 + 0];
        const float oy = ray_o[rb * 3 + 1];
        const float oz = ray_o[rb * 3 + 2];
        const float ix = 1.0f / ray_d[rb * 3 + 0];
        const float iy = 1.0f / ray_d[rb * 3 + 1];
        const float iz = 1.0f / ray_d[rb * 3 + 2];
        s_ray[tid][0] = ix;
        s_ray[tid][1] = iy;
        s_ray[tid][2] = iz;
        s_ray[tid][3] = -ox * ix;
        s_ray[tid][4] = -oy * iy;
        s_ray[tid][5] = -oz * iz;
        s_cnt[tid] = 0;
    }

    // ---- load this thread's 4 resident voxels (once per CTA, serves 4 rays) ----
    float vx[VPT], vy[VPT], vz[VPT], vh[VPT];
    #pragma unroll
    for (int k = 0; k < VPT; k++) {
        const int v = k * THREADS + tid;
        vx[k] = positions[v * 3 + 0];
        vy[k] = positions[v * 3 + 1];
        vz[k] = positions[v * 3 + 2];
        vh[k] = 0.5f * sizes[v];
    }
    __syncthreads();

    // ---------------- Phase 1: 4 rays x 4 resident voxels per thread ----------------
    #pragma unroll
    for (int r = 0; r < RAYS_PER_CTA; r++) {
        const float ix = s_ray[r][0], iy = s_ray[r][1], iz = s_ray[r][2];
        const float nx = s_ray[r][3], ny = s_ray[r][4], nz = s_ray[r][5];
        const float axr = fabsf(ix), ayr = fabsf(iy), azr = fabsf(iz);

        #pragma unroll
        for (int k = 0; k < VPT; k++) {
            const float tcx = fmaf(vx[k], ix, nx);
            const float tcy = fmaf(vy[k], iy, ny);
            const float tcz = fmaf(vz[k], iz, nz);
            const float hx = vh[k] * axr, hy = vh[k] * ayr, hz = vh[k] * azr;

            const float tn = fmaxf(fmaxf(tcx - hx, tcy - hy), tcz - hz);
            const float tf = fminf(fminf(tcx + hx, tcy + hy), tcz + hz);

            if (tf > fmaxf(tn, 0.0f)) {
                const int slot = atomicAdd(&s_cnt[r], 1);
                if (slot < CAP) {
                    const int v = k * THREADS + tid;
                    s_keys[r][slot] = ((unsigned long long)f2u(tn) << 32) | (unsigned)v;
                    s_tw[r][slot]   = tf;
                }
            }
        }
    }
    __syncthreads();

    // ---------------- Tail pass A: chunk-split across warp pairs ----------------
    // warp w takes chunks 0,2,4,... and warp w+4 takes chunks 1,3,5,... of ray w&3.
    // For n <= 32 this is identical work to the single-warp version (warp w+4 idles).
    const int ray  = warp & (RAYS_PER_CTA - 1);
    const int half = warp >> 2;                    // 0 or 1 -> starting chunk
    const int n    = min(s_cnt[ray], CAP);
    const int b    = blockIdx.x * RAYS_PER_CTA + ray;

    // SH degree-2 basis, reference order: [1, y, z, x, xy, yz, 3z^2-1, xz, x^2-y^2]
    const float dx = ray_d[b * 3 + 0];
    const float dy = ray_d[b * 3 + 1];
    const float dz = ray_d[b * 3 + 2];
    float sh[N_SH];
    sh[0] = 1.0f;
    sh[1] = dy;  sh[2] = dz;  sh[3] = dx;
    sh[4] = dx * dy;  sh[5] = dy * dz;
    sh[6] = 3.0f * dz * dz - 1.0f;
    sh[7] = dx * dz;  sh[8] = dx * dx - dy * dy;

    for (int base = half * 32; base < n; base += 64) {
        const int e = base + lane;
        if (e < n) {
            const unsigned long long key = s_keys[ray][e];
            const unsigned v = (unsigned)(key & 0xFFFFFFFFu);
            unsigned tu = (unsigned)(key >> 32);
            const float tn = __uint_as_float((tu & 0x80000000u) ? (tu & 0x7FFFFFFFu) : ~tu);
            const float tf = s_tw[ray][e];

            const float sigma = __expf(densities[v]);
            const float span  = tf - tn;
            const float delta = span * (1.0f / (float)NS);
            const float alpha = 1.0f - __expf(-sigma * delta);
            const float bse   = 1.0f - alpha + 1e-8f;

            float pw = 1.0f, ws = 0.0f, dp = 0.0f;
            #pragma unroll
            for (int s = 0; s < NS; s++) {
                const float w  = alpha * pw;
                const float ts = tn + span * ((float)s / (float)(NS - 1));
                ws += w;
                dp += w * ts;
                pw *= bse;
            }

            const float* c = colors + v * (3 * N_SH);
            float a0 = 0.0f, a1 = 0.0f, a2 = 0.0f;
            #pragma unroll
            for (int k = 0; k < N_SH; k++) {
                a0 += sh[k] * c[k];
                a1 += sh[k] * c[N_SH + k];
                a2 += sh[k] * c[2 * N_SH + k];
            }

            s_tw[ray][e] = ws;
            s_dp[ray][e] = dp;
            s_cr[ray][e] = fast_sigmoid(a0);
            s_cg[ray][e] = fast_sigmoid(a1);
            s_cb[ray][e] = fast_sigmoid(a2);
        }
    }
    __syncthreads();

    // ---------------- Tail pass B: warps 0-3 only (warp w -> ray w) ----------------
    if (warp >= RAYS_PER_CTA) return;

    float rA = 0.0f, gA = 0.0f, bA = 0.0f, dA = 0.0f, wA = 0.0f;

    for (int base = 0; base < n; base += 32) {
        const int e = base + lane;
        if (e < n) {
            const unsigned long long ke = s_keys[warp][e];
            float T = 1.0f;
            for (int j = 0; j < n; j++) {
                const float om = 1.0f - s_tw[warp][j];
                T *= (s_keys[warp][j] < ke) ? om : 1.0f;
            }
            const float procf   = (T >= EARLY_STOP_T) ? 1.0f : 0.0f;
            const float ws      = s_tw[warp][e];
            const float contrib = T * ws * procf;
            rA += contrib * s_cr[warp][e];
            gA += contrib * s_cg[warp][e];
            bA += contrib * s_cb[warp][e];
            dA += T * procf * s_dp[warp][e];
            wA += contrib;
        }
    }

    // warp reductions
    #pragma unroll
    for (int off = 16; off > 0; off >>= 1) {
        rA += __shfl_down_sync(FULL, rA, off);
        gA += __shfl_down_sync(FULL, gA, off);
        bA += __shfl_down_sync(FULL, bA, off);
        dA += __shfl_down_sync(FULL, dA, off);
        wA += __shfl_down_sync(FULL, wA, off);
    }

    if (lane == 0) {
        out[b * 3 + 0] = rA;
        out[b * 3 + 1] = gA;
        out[b * 3 + 2] = bA;
        out[NUM_RAYS * 3 + b] = (n > 0) ? dA : FAR_PLANE;   // has_hit == (n > 0)
        out[NUM_RAYS * 4 + b] = wA;
    }
}

extern "C" void kernel_launch(void* const* d_in, const int* in_sizes, int n_in,
                              void* d_out, int out_size) {
    const float* positions = (const float*)d_in[0];
    const float* sizes     = (const float*)d_in[1];
    const float* densities = (const float*)d_in[2];
    const float* colors    = (const float*)d_in[3];
    const float* ray_o     = (const float*)d_in[4];
    const float* ray_d     = (const float*)d_in[5];
    float* out = (float*)d_out;

    voxel_raster_kernel<<<NUM_RAYS / RAYS_PER_CTA, THREADS>>>(
        positions, sizes, densities, colors, ray_o, ray_d, out);
}